// round 2
// baseline (speedup 1.0000x reference)
#include <cuda_runtime.h>
#include <cstdint>

#define Hc   256
#define Bc   64
#define Tc   256
#define Ec   300
#define NB   128
#define NT   256
typedef unsigned long long ull;

// ---------------- device scratch (no allocations allowed) ----------------
__device__ float g_pre0[(size_t)Tc * 1024 * Bc];   // [t][gatecol 0..1023][b]  (64 MB)
__device__ float g_h0[2][Hc * Bc];                 // layer0 h, double buffered, [unit][b]
__device__ float g_h1[2][Hc * Bc];                 // layer1 h
__device__ volatile unsigned g_flags[NB];
__device__ int g_is64;

// ---------------- helpers ----------------
__device__ __forceinline__ void fma2(ull& d, ull a, ull b) {
    asm("fma.rn.f32x2 %0, %1, %2, %0;" : "+l"(d) : "l"(a), "l"(b));
}
__device__ __forceinline__ ull dup2(float x) {
    ull r;
    asm("mov.b64 %0, {%1, %1};" : "=l"(r) : "f"(x));
    return r;
}
__device__ __forceinline__ float2 unpk(ull v) {
    float2 r;
    asm("mov.b64 {%0, %1}, %2;" : "=f"(r.x), "=f"(r.y) : "l"(v));
    return r;
}
__device__ __forceinline__ float sigf(float x)  { return 1.0f / (1.0f + __expf(-x)); }
__device__ __forceinline__ float tanhf_(float x){ return 2.0f / (1.0f + __expf(-2.0f * x)) - 1.0f; }

// Flag-array global barrier: each CTA publishes its epoch to a distinct word,
// warp 0 polls all 128 flags in parallel (4 per lane). No atomic serialization.
__device__ __forceinline__ void gbarrier(unsigned epoch) {
    __threadfence();          // release: make this thread's stores visible
    __syncthreads();          // all threads of CTA fenced before flag goes up
    if (threadIdx.x < 32) {
        if (threadIdx.x == 0) g_flags[blockIdx.x] = epoch;
        const unsigned i0 = threadIdx.x;
        bool ok;
        do {
            ok = (g_flags[i0] >= epoch) & (g_flags[i0 + 32] >= epoch) &
                 (g_flags[i0 + 64] >= epoch) & (g_flags[i0 + 96] >= epoch);
        } while (!__all_sync(0xffffffffu, ok));
        __threadfence();      // acquire
    }
    __syncthreads();
}

// ---------------- kernel: int32 vs int64 token detector ----------------
// Tokens are in [0, 50000), so if x is int64 (LE) every odd 32-bit word is 0.
__global__ void k_detect(const int* __restrict__ x) {
    int v = 0;
    for (int i = threadIdx.x * 2 + 1; i < Bc * Tc; i += 1024) v |= x[i];
    int any = __syncthreads_or(v);
    if (threadIdx.x == 0) g_is64 = (any == 0) ? 1 : 0;
}

// ---------------- kernel: pre0[t][c][b] = b0[c] + emb[x[b,t]] . W0x[:,c] ----------------
// grid (4 col-chunks, 256 t). Block stages the 64 token embeddings for its t once
// (smem [e][b], pad 66), then computes a 256-col x 64-batch tile.
// Thread tile: 4 cols x 16 batches (8 f32x2 pairs) -> 32 FFMA2 per e,
// fed by 8 broadcast LDS.64 + 1 coalesced LDG.128.
__global__ void __launch_bounds__(256) k_pre(const int* __restrict__ x,
                                             const float* __restrict__ emb,
                                             const float* __restrict__ W0,
                                             const float* __restrict__ b0) {
    extern __shared__ float semb[];  // [Ec][66]
    const int t = blockIdx.y, ct = blockIdx.x;
    const int tid = threadIdx.x, lane = tid & 31, w = tid >> 5;
    const int is64 = g_is64;

    // gather 64 embedding rows, transposed: semb[e*66 + b]
    for (int bb = w; bb < Bc; bb += 8) {
        int idx = bb * Tc + t;
        int tok = is64 ? x[2 * idx] : x[idx];
        const float* er = emb + (size_t)tok * Ec;
        for (int e = lane; e < Ec; e += 32) semb[e * 66 + bb] = er[e];
    }
    __syncthreads();

    const int cg = tid & 63, bg = tid >> 6;
    const int c0 = ct * 256 + cg * 4;

    ull a0[8], a1[8], a2[8], a3[8];
#pragma unroll
    for (int j = 0; j < 8; j++) { a0[j] = 0ull; a1[j] = 0ull; a2[j] = 0ull; a3[j] = 0ull; }

#pragma unroll 4
    for (int e = 0; e < Ec; e++) {
        float4 wv = __ldg((const float4*)(W0 + (size_t)e * 1024 + c0));
        ull w0 = dup2(wv.x), w1 = dup2(wv.y), w2 = dup2(wv.z), w3 = dup2(wv.w);
        const ull* sp = (const ull*)(semb + e * 66 + bg * 16);
        ull p0 = sp[0], p1 = sp[1], p2 = sp[2], p3 = sp[3];
        ull p4 = sp[4], p5 = sp[5], p6 = sp[6], p7 = sp[7];
        fma2(a0[0], p0, w0); fma2(a0[1], p1, w0); fma2(a0[2], p2, w0); fma2(a0[3], p3, w0);
        fma2(a0[4], p4, w0); fma2(a0[5], p5, w0); fma2(a0[6], p6, w0); fma2(a0[7], p7, w0);
        fma2(a1[0], p0, w1); fma2(a1[1], p1, w1); fma2(a1[2], p2, w1); fma2(a1[3], p3, w1);
        fma2(a1[4], p4, w1); fma2(a1[5], p5, w1); fma2(a1[6], p6, w1); fma2(a1[7], p7, w1);
        fma2(a2[0], p0, w2); fma2(a2[1], p1, w2); fma2(a2[2], p2, w2); fma2(a2[3], p3, w2);
        fma2(a2[4], p4, w2); fma2(a2[5], p5, w2); fma2(a2[6], p6, w2); fma2(a2[7], p7, w2);
        fma2(a3[0], p0, w3); fma2(a3[1], p1, w3); fma2(a3[2], p2, w3); fma2(a3[3], p3, w3);
        fma2(a3[4], p4, w3); fma2(a3[5], p5, w3); fma2(a3[6], p6, w3); fma2(a3[7], p7, w3);
    }

    float4 bb4 = __ldg((const float4*)(b0 + c0));
    float bs[4] = {bb4.x, bb4.y, bb4.z, bb4.w};
    ull* accs[4] = {a0, a1, a2, a3};
#pragma unroll
    for (int j = 0; j < 4; j++) {
        float* op = g_pre0 + ((size_t)t * 1024 + c0 + j) * Bc + bg * 16;
#pragma unroll
        for (int p = 0; p < 8; p++) {
            float2 v = unpk(accs[j][p]);
            v.x += bs[j]; v.y += bs[j];
            *(float2*)(op + 2 * p) = v;
        }
    }
}

// ---------------- kernel: persistent 2-layer pipelined recurrence ----------------
// 128 CTAs x 256 thr; CTA owns 2 hidden units of BOTH layers for all 64 batches.
// 257 supersteps; layer1 lags layer0 by one step -> one global barrier/superstep.
// Dot phase: warp w covers k in [32w,32w+32); lane owns batch pair (2*lane,2*lane+1).
// Fused pass over h0[s-1] feeds layer0 gates (W0h) AND layer1 x-proj (W1x);
// tail pass over h1[s-2] feeds layer1 (W1h). Split-K partials reduced via smem.
__global__ void __launch_bounds__(256) k_rnn(const float* __restrict__ W0,
                                             const float* __restrict__ W1,
                                             const float* __restrict__ b1,
                                             float* __restrict__ out) {
    extern __shared__ char sm[];
    ull*   swf  = (ull*)sm;                    // fused weights: [k][16 cols dup'd]  32KB
    ull*   swt  = swf + 256 * 16;              // tail  weights: [k][8 cols dup'd]   16KB
    float* gg   = (float*)(swt + 256 * 8);     // partials [16 cols][8 warps][64 b]  32KB
    float* b1sh = gg + 16 * 8 * 64;

    const int tid = threadIdx.x, lane = tid & 31, w = tid >> 5, bid = blockIdx.x;

    // Stage recurrent weights (lane-duplicated pairs) into smem once.
    // Local col c in [0,8): gate g=c>>1, unit u=c&1; global col G = g*256 + bid*2 + u.
    for (int idx = tid; idx < 256 * 8; idx += NT) {
        int k = idx >> 3, c = idx & 7;
        int G = ((c >> 1) << 8) + bid * 2 + (c & 1);
        swf[k * 16 + c]     = dup2(__ldg(W0 + (size_t)(Ec + k) * 1024 + G));  // W0h
        swf[k * 16 + 8 + c] = dup2(__ldg(W1 + (size_t)k * 1024 + G));         // W1x
        swt[k * 8 + c]      = dup2(__ldg(W1 + (size_t)(Hc + k) * 1024 + G));  // W1h
    }
    if (tid < 8) {
        int c = tid;
        int G = ((c >> 1) << 8) + bid * 2 + (c & 1);
        b1sh[c] = __ldg(b1 + G);
    }
    // zero this CTA's state slices (fresh per launch -> deterministic across replays)
    if (tid < 128) {
        int off = bid * 128 + tid;
        g_h0[0][off] = 0.f; g_h0[1][off] = 0.f;
        g_h1[0][off] = 0.f; g_h1[1][off] = 0.f;
    }
    float creg = 0.f;  // cell state owned by this (layer,unit,batch) thread
    gbarrier(1u);

    const int l_ = tid >> 7, u_ = (tid >> 6) & 1, b_ = tid & 63;
    const int U_ = bid * 2 + u_;

    for (int s = 0; s <= Tc; s++) {
        const float* rb0 = g_h0[s & 1];
        const float* rb1 = g_h1[s & 1];

        // prefetch this thread's 4 precomputed x-proj gate values (cold HBM)
        float pf[4] = {0.f, 0.f, 0.f, 0.f};
        if (l_ == 0 && s < Tc) {
#pragma unroll
            for (int g = 0; g < 4; g++)
                pf[g] = __ldg(g_pre0 + ((size_t)s * 1024 + g * 256 + U_) * Bc + b_);
        }

        ull aA[8], aB[8];
#pragma unroll
        for (int j = 0; j < 8; j++) { aA[j] = 0ull; aB[j] = 0ull; }

        {   // fused pass over h0[s-1]
            const ull* hp = (const ull*)rb0 + w * 32 * 32 + lane;
            const ulonglong2* wp = (const ulonglong2*)(swf + (size_t)w * 32 * 16);
#pragma unroll 8
            for (int kk = 0; kk < 32; kk++) {
                ull hv = __ldcg(hp + kk * 32);   // .cg: L1 not coherent across SMs
                ulonglong2 q0 = wp[kk * 8 + 0], q1 = wp[kk * 8 + 1];
                ulonglong2 q2 = wp[kk * 8 + 2], q3 = wp[kk * 8 + 3];
                ulonglong2 q4 = wp[kk * 8 + 4], q5 = wp[kk * 8 + 5];
                ulonglong2 q6 = wp[kk * 8 + 6], q7 = wp[kk * 8 + 7];
                fma2(aA[0], hv, q0.x); fma2(aA[1], hv, q0.y);
                fma2(aA[2], hv, q1.x); fma2(aA[3], hv, q1.y);
                fma2(aA[4], hv, q2.x); fma2(aA[5], hv, q2.y);
                fma2(aA[6], hv, q3.x); fma2(aA[7], hv, q3.y);
                fma2(aB[0], hv, q4.x); fma2(aB[1], hv, q4.y);
                fma2(aB[2], hv, q5.x); fma2(aB[3], hv, q5.y);
                fma2(aB[4], hv, q6.x); fma2(aB[5], hv, q6.y);
                fma2(aB[6], hv, q7.x); fma2(aB[7], hv, q7.y);
            }
        }
        {   // tail pass over h1[s-2]
            const ull* hp = (const ull*)rb1 + w * 32 * 32 + lane;
            const ulonglong2* wp = (const ulonglong2*)(swt + (size_t)w * 32 * 8);
#pragma unroll 8
            for (int kk = 0; kk < 32; kk++) {
                ull hv = __ldcg(hp + kk * 32);
                ulonglong2 q0 = wp[kk * 4 + 0], q1 = wp[kk * 4 + 1];
                ulonglong2 q2 = wp[kk * 4 + 2], q3 = wp[kk * 4 + 3];
                fma2(aB[0], hv, q0.x); fma2(aB[1], hv, q0.y);
                fma2(aB[2], hv, q1.x); fma2(aB[3], hv, q1.y);
                fma2(aB[4], hv, q2.x); fma2(aB[5], hv, q2.y);
                fma2(aB[6], hv, q3.x); fma2(aB[7], hv, q3.y);
            }
        }
        // publish split-K partials: gg[col][warp][batch]
#pragma unroll
        for (int c = 0; c < 8; c++) {
            ((ull*)gg)[(c * 8 + w) * 32 + lane]       = aA[c];
            ((ull*)gg)[((8 + c) * 8 + w) * 32 + lane] = aB[c];
        }
        __syncthreads();

        // phase 2: thread (l_,u_,b_) reduces its 4 gate columns and updates state
        const bool active = (l_ == 0) ? (s < Tc) : (s >= 1);
        if (active) {
            float gate[4];
#pragma unroll
            for (int g = 0; g < 4; g++) {
                int c = l_ * 8 + g * 2 + u_;
                const float* pp = gg + (c * 8) * 64 + b_;
                float sum = pp[0] + pp[64] + pp[128] + pp[192] +
                            pp[256] + pp[320] + pp[384] + pp[448];
                gate[g] = sum + ((l_ == 0) ? pf[g] : b1sh[g * 2 + u_]);
            }
            float ii = sigf(gate[0]);
            float jj = tanhf_(gate[1]);
            float ff = sigf(gate[2] + 1.0f);       // FORGET_BIAS
            float oo = sigf(gate[3]);
            creg = creg * ff + ii * jj;
            float h = tanhf_(creg) * oo;
            if (l_ == 0) {
                g_h0[(s + 1) & 1][U_ * Bc + b_] = h;
            } else if (s < Tc) {
                g_h1[(s + 1) & 1][U_ * Bc + b_] = h;
            } else {
                out[b_ * Hc + U_] = h;             // h1[T-1] -> final output
            }
        }
        gbarrier((unsigned)(s + 2));
    }
}

// ---------------- kernel: reset barrier flags for next graph replay ----------------
__global__ void k_reset() {
    if (threadIdx.x < NB) g_flags[threadIdx.x] = 0u;
}

// ---------------- host launcher ----------------
extern "C" void kernel_launch(void* const* d_in, const int* in_sizes, int n_in,
                              void* d_out, int out_size) {
    const int*   x   = (const int*)d_in[0];
    const float* emb = (const float*)d_in[1];
    const float* W0  = (const float*)d_in[2];
    const float* b0  = (const float*)d_in[3];
    const float* W1  = (const float*)d_in[4];
    const float* b1  = (const float*)d_in[5];
    float*       out = (float*)d_out;
    (void)in_sizes; (void)n_in; (void)out_size;

    const int smem_pre = Ec * 66 * 4;                              // 79200 B
    const int smem_rnn = 256 * 16 * 8 + 256 * 8 * 8 + 16 * 8 * 64 * 4 + 64;  // ~82 KB

    static bool attr_done = false;
    if (!attr_done) {
        cudaFuncSetAttribute(k_pre, cudaFuncAttributeMaxDynamicSharedMemorySize, smem_pre);
        cudaFuncSetAttribute(k_rnn, cudaFuncAttributeMaxDynamicSharedMemorySize, smem_rnn);
        attr_done = true;
    }

    k_detect<<<1, 512>>>(x);
    k_pre<<<dim3(4, 256), 256, smem_pre>>>(x, emb, W0, b0);
    k_rnn<<<NB, NT, smem_rnn>>>(W0, W1, b1, out);
    k_reset<<<1, 128>>>();
}

// round 3
// speedup vs baseline: 1.0769x; 1.0769x over previous
#include <cuda_runtime.h>
#include <cstdint>

#define Hc   256
#define Bc   64
#define Tc   256
#define Ec   300
#define NB   128
#define NT   256
typedef unsigned long long ull;

// ---------------- device scratch (no allocations allowed) ----------------
__device__ float g_pre0[(size_t)Tc * 1024 * Bc];   // [t][gatecol 0..1023][b]  (64 MB)
__device__ float g_h0[2][Hc * Bc];                 // layer0 h, double buffered, [unit][b]
__device__ float g_h1[2][Hc * Bc];                 // layer1 h
__device__ unsigned g_flags[NB * 8];               // 32B-padded per-CTA epoch flags
__device__ unsigned g_gen;                         // broadcast generation word
__device__ int g_is64;

// ---------------- helpers ----------------
__device__ __forceinline__ void fma2(ull& d, ull a, ull b) {
    asm("fma.rn.f32x2 %0, %1, %2, %0;" : "+l"(d) : "l"(a), "l"(b));
}
__device__ __forceinline__ ull dup2(float x) {
    ull r;
    asm("mov.b64 %0, {%1, %1};" : "=l"(r) : "f"(x));
    return r;
}
__device__ __forceinline__ float2 unpk(ull v) {
    float2 r;
    asm("mov.b64 {%0, %1}, %2;" : "=f"(r.x), "=f"(r.y) : "l"(v));
    return r;
}
__device__ __forceinline__ float sigf(float x)  { return 1.0f / (1.0f + __expf(-x)); }
__device__ __forceinline__ float tanhf_(float x){ return 2.0f / (1.0f + __expf(-2.0f * x)) - 1.0f; }

__device__ __forceinline__ void st_rel(unsigned* p, unsigned v) {
    asm volatile("st.release.gpu.global.u32 [%0], %1;" :: "l"(p), "r"(v) : "memory");
}
__device__ __forceinline__ unsigned ld_acq(const unsigned* p) {
    unsigned v;
    asm volatile("ld.acquire.gpu.global.u32 %0, [%1];" : "=r"(v) : "l"(p) : "memory");
    return v;
}

// Grid barrier v2: one release-store per CTA to a padded flag; CTA0/warp0
// aggregates 128 flags and publishes ONE generation word; everyone else spins
// on that single word with one acquire-load per CTA. No per-thread fences,
// no chip-wide poll flood.
__device__ __forceinline__ void gbar(int bid, int tid, unsigned epoch) {
    __syncthreads();                         // CTA-scope cumulativity for h stores
    if (tid == 0) st_rel(&g_flags[bid * 8], epoch);
    if (bid == 0 && tid < 32) {
        bool ok;
        do {
            unsigned v0 = ld_acq(&g_flags[tid * 8]);
            unsigned v1 = ld_acq(&g_flags[(tid + 32) * 8]);
            unsigned v2 = ld_acq(&g_flags[(tid + 64) * 8]);
            unsigned v3 = ld_acq(&g_flags[(tid + 96) * 8]);
            ok = (v0 >= epoch) & (v1 >= epoch) & (v2 >= epoch) & (v3 >= epoch);
        } while (!__all_sync(0xffffffffu, ok));
        if (tid == 0) st_rel(&g_gen, epoch);
    } else if (tid == 0) {
        while (ld_acq(&g_gen) < epoch) {}
    }
    __syncthreads();                         // publish acquire to whole CTA
}

// ---------------- kernel: int32 vs int64 token detector ----------------
// Tokens are in [0, 50000), so if x is int64 (LE) every odd 32-bit word is 0.
__global__ void k_detect(const int* __restrict__ x) {
    int v = 0;
    for (int i = threadIdx.x * 2 + 1; i < Bc * Tc; i += 1024) v |= x[i];
    int any = __syncthreads_or(v);
    if (threadIdx.x == 0) g_is64 = (any == 0) ? 1 : 0;
}

// ---------------- kernel: pre0[t][c][b] = b0[c] + emb[x[b,t]] . W0x[:,c] ----------------
__global__ void __launch_bounds__(256) k_pre(const int* __restrict__ x,
                                             const float* __restrict__ emb,
                                             const float* __restrict__ W0,
                                             const float* __restrict__ b0) {
    extern __shared__ float semb[];  // [Ec][66]
    const int t = blockIdx.y, ct = blockIdx.x;
    const int tid = threadIdx.x, lane = tid & 31, w = tid >> 5;
    const int is64 = g_is64;

    for (int bb = w; bb < Bc; bb += 8) {
        int idx = bb * Tc + t;
        int tok = is64 ? x[2 * idx] : x[idx];
        const float* er = emb + (size_t)tok * Ec;
        for (int e = lane; e < Ec; e += 32) semb[e * 66 + bb] = er[e];
    }
    __syncthreads();

    const int cg = tid & 63, bg = tid >> 6;
    const int c0 = ct * 256 + cg * 4;

    ull a0[8], a1[8], a2[8], a3[8];
#pragma unroll
    for (int j = 0; j < 8; j++) { a0[j] = 0ull; a1[j] = 0ull; a2[j] = 0ull; a3[j] = 0ull; }

#pragma unroll 4
    for (int e = 0; e < Ec; e++) {
        float4 wv = __ldg((const float4*)(W0 + (size_t)e * 1024 + c0));
        ull w0 = dup2(wv.x), w1 = dup2(wv.y), w2 = dup2(wv.z), w3 = dup2(wv.w);
        const ull* sp = (const ull*)(semb + e * 66 + bg * 16);
        ull p0 = sp[0], p1 = sp[1], p2 = sp[2], p3 = sp[3];
        ull p4 = sp[4], p5 = sp[5], p6 = sp[6], p7 = sp[7];
        fma2(a0[0], p0, w0); fma2(a0[1], p1, w0); fma2(a0[2], p2, w0); fma2(a0[3], p3, w0);
        fma2(a0[4], p4, w0); fma2(a0[5], p5, w0); fma2(a0[6], p6, w0); fma2(a0[7], p7, w0);
        fma2(a1[0], p0, w1); fma2(a1[1], p1, w1); fma2(a1[2], p2, w1); fma2(a1[3], p3, w1);
        fma2(a1[4], p4, w1); fma2(a1[5], p5, w1); fma2(a1[6], p6, w1); fma2(a1[7], p7, w1);
        fma2(a2[0], p0, w2); fma2(a2[1], p1, w2); fma2(a2[2], p2, w2); fma2(a2[3], p3, w2);
        fma2(a2[4], p4, w2); fma2(a2[5], p5, w2); fma2(a2[6], p6, w2); fma2(a2[7], p7, w2);
        fma2(a3[0], p0, w3); fma2(a3[1], p1, w3); fma2(a3[2], p2, w3); fma2(a3[3], p3, w3);
        fma2(a3[4], p4, w3); fma2(a3[5], p5, w3); fma2(a3[6], p6, w3); fma2(a3[7], p7, w3);
    }

    float4 bb4 = __ldg((const float4*)(b0 + c0));
    float bs[4] = {bb4.x, bb4.y, bb4.z, bb4.w};
    ull* accs[4] = {a0, a1, a2, a3};
#pragma unroll
    for (int j = 0; j < 4; j++) {
        float* op = g_pre0 + ((size_t)t * 1024 + c0 + j) * Bc + bg * 16;
#pragma unroll
        for (int p = 0; p < 8; p++) {
            float2 v = unpk(accs[j][p]);
            v.x += bs[j]; v.y += bs[j];
            *(float2*)(op + 2 * p) = v;
        }
    }
}

// ---------------- kernel: persistent 2-layer pipelined recurrence ----------------
// 128 CTAs x 256 thr; CTA owns 2 hidden units of BOTH layers for all 64 batches.
// 257 supersteps; layer1 lags layer0 by one step -> one global barrier/superstep.
__global__ void __launch_bounds__(256) k_rnn(const float* __restrict__ W0,
                                             const float* __restrict__ W1,
                                             const float* __restrict__ b1,
                                             float* __restrict__ out) {
    extern __shared__ char sm[];
    ull*   swf  = (ull*)sm;                    // fused weights: [k][16 cols dup'd]  32KB
    ull*   swt  = swf + 256 * 16;              // tail  weights: [k][8 cols dup'd]   16KB
    float* gg   = (float*)(swt + 256 * 8);     // partials [16 cols][8 warps][64 b]  32KB
    float* b1sh = gg + 16 * 8 * 64;

    const int tid = threadIdx.x, lane = tid & 31, w = tid >> 5, bid = blockIdx.x;

    for (int idx = tid; idx < 256 * 8; idx += NT) {
        int k = idx >> 3, c = idx & 7;
        int G = ((c >> 1) << 8) + bid * 2 + (c & 1);
        swf[k * 16 + c]     = dup2(__ldg(W0 + (size_t)(Ec + k) * 1024 + G));  // W0h
        swf[k * 16 + 8 + c] = dup2(__ldg(W1 + (size_t)k * 1024 + G));         // W1x
        swt[k * 8 + c]      = dup2(__ldg(W1 + (size_t)(Hc + k) * 1024 + G));  // W1h
    }
    if (tid < 8) {
        int c = tid;
        int G = ((c >> 1) << 8) + bid * 2 + (c & 1);
        b1sh[c] = __ldg(b1 + G);
    }
    if (tid < 128) {
        int off = bid * 128 + tid;
        g_h0[0][off] = 0.f; g_h0[1][off] = 0.f;
        g_h1[0][off] = 0.f; g_h1[1][off] = 0.f;
    }
    float creg = 0.f;  // cell state owned by this (layer,unit,batch) thread
    gbar(bid, tid, 1u);

    const int l_ = tid >> 7, u_ = (tid >> 6) & 1, b_ = tid & 63;
    const int U_ = bid * 2 + u_;

    for (int s = 0; s <= Tc; s++) {
        const float* rb0 = g_h0[s & 1];
        const float* rb1 = g_h1[s & 1];

        // prefetch this thread's 4 precomputed x-proj gate values (cold HBM)
        float pf[4] = {0.f, 0.f, 0.f, 0.f};
        if (l_ == 0 && s < Tc) {
#pragma unroll
            for (int g = 0; g < 4; g++)
                pf[g] = __ldg(g_pre0 + ((size_t)s * 1024 + g * 256 + U_) * Bc + b_);
        }

        ull aA[8], aB[8];
#pragma unroll
        for (int j = 0; j < 8; j++) { aA[j] = 0ull; aB[j] = 0ull; }

        {   // fused pass over h0[s-1]: layer0 gates (W0h) + layer1 x-proj (W1x)
            const ull* hp = (const ull*)rb0 + w * 32 * 32 + lane;
            const ulonglong2* wp = (const ulonglong2*)(swf + (size_t)w * 32 * 16);
#pragma unroll 8
            for (int kk = 0; kk < 32; kk++) {
                ull hv = __ldcg(hp + kk * 32);   // .cg: L1 not coherent across SMs
                ulonglong2 q0 = wp[kk * 8 + 0], q1 = wp[kk * 8 + 1];
                ulonglong2 q2 = wp[kk * 8 + 2], q3 = wp[kk * 8 + 3];
                ulonglong2 q4 = wp[kk * 8 + 4], q5 = wp[kk * 8 + 5];
                ulonglong2 q6 = wp[kk * 8 + 6], q7 = wp[kk * 8 + 7];
                fma2(aA[0], hv, q0.x); fma2(aA[1], hv, q0.y);
                fma2(aA[2], hv, q1.x); fma2(aA[3], hv, q1.y);
                fma2(aA[4], hv, q2.x); fma2(aA[5], hv, q2.y);
                fma2(aA[6], hv, q3.x); fma2(aA[7], hv, q3.y);
                fma2(aB[0], hv, q4.x); fma2(aB[1], hv, q4.y);
                fma2(aB[2], hv, q5.x); fma2(aB[3], hv, q5.y);
                fma2(aB[4], hv, q6.x); fma2(aB[5], hv, q6.y);
                fma2(aB[6], hv, q7.x); fma2(aB[7], hv, q7.y);
            }
        }
        {   // tail pass over h1[s-2]: layer1 hidden proj (W1h)
            const ull* hp = (const ull*)rb1 + w * 32 * 32 + lane;
            const ulonglong2* wp = (const ulonglong2*)(swt + (size_t)w * 32 * 8);
#pragma unroll 8
            for (int kk = 0; kk < 32; kk++) {
                ull hv = __ldcg(hp + kk * 32);
                ulonglong2 q0 = wp[kk * 4 + 0], q1 = wp[kk * 4 + 1];
                ulonglong2 q2 = wp[kk * 4 + 2], q3 = wp[kk * 4 + 3];
                fma2(aB[0], hv, q0.x); fma2(aB[1], hv, q0.y);
                fma2(aB[2], hv, q1.x); fma2(aB[3], hv, q1.y);
                fma2(aB[4], hv, q2.x); fma2(aB[5], hv, q2.y);
                fma2(aB[6], hv, q3.x); fma2(aB[7], hv, q3.y);
            }
        }
#pragma unroll
        for (int c = 0; c < 8; c++) {
            ((ull*)gg)[(c * 8 + w) * 32 + lane]       = aA[c];
            ((ull*)gg)[((8 + c) * 8 + w) * 32 + lane] = aB[c];
        }
        __syncthreads();

        const bool active = (l_ == 0) ? (s < Tc) : (s >= 1);
        if (active) {
            float gate[4];
#pragma unroll
            for (int g = 0; g < 4; g++) {
                int c = l_ * 8 + g * 2 + u_;
                const float* pp = gg + (c * 8) * 64 + b_;
                float sum = pp[0] + pp[64] + pp[128] + pp[192] +
                            pp[256] + pp[320] + pp[384] + pp[448];
                gate[g] = sum + ((l_ == 0) ? pf[g] : b1sh[g * 2 + u_]);
            }
            float ii = sigf(gate[0]);
            float jj = tanhf_(gate[1]);
            float ff = sigf(gate[2] + 1.0f);       // FORGET_BIAS
            float oo = sigf(gate[3]);
            creg = creg * ff + ii * jj;
            float h = tanhf_(creg) * oo;
            if (l_ == 0) {
                g_h0[(s + 1) & 1][U_ * Bc + b_] = h;
            } else if (s < Tc) {
                g_h1[(s + 1) & 1][U_ * Bc + b_] = h;
            } else {
                out[b_ * Hc + U_] = h;             // h1[T-1] -> final output
            }
        }
        if (s < Tc) gbar(bid, tid, (unsigned)(s + 2));  // no barrier after last step
    }
}

// ---------------- kernel: reset barrier state for next graph replay ----------------
__global__ void k_reset() {
    int i = blockIdx.x * blockDim.x + threadIdx.x;
    if (i < NB * 8) g_flags[i] = 0u;
    if (i == 0) g_gen = 0u;
}

// ---------------- host launcher ----------------
extern "C" void kernel_launch(void* const* d_in, const int* in_sizes, int n_in,
                              void* d_out, int out_size) {
    const int*   x   = (const int*)d_in[0];
    const float* emb = (const float*)d_in[1];
    const float* W0  = (const float*)d_in[2];
    const float* b0  = (const float*)d_in[3];
    const float* W1  = (const float*)d_in[4];
    const float* b1  = (const float*)d_in[5];
    float*       out = (float*)d_out;
    (void)in_sizes; (void)n_in; (void)out_size;

    const int smem_pre = Ec * 66 * 4;                              // 79200 B
    const int smem_rnn = 256 * 16 * 8 + 256 * 8 * 8 + 16 * 8 * 64 * 4 + 64;  // ~82 KB

    static bool attr_done = false;
    if (!attr_done) {
        cudaFuncSetAttribute(k_pre, cudaFuncAttributeMaxDynamicSharedMemorySize, smem_pre);
        cudaFuncSetAttribute(k_rnn, cudaFuncAttributeMaxDynamicSharedMemorySize, smem_rnn);
        attr_done = true;
    }

    k_detect<<<1, 512>>>(x);
    k_pre<<<dim3(4, 256), 256, smem_pre>>>(x, emb, W0, b0);
    k_rnn<<<NB, NT, smem_rnn>>>(W0, W1, b1, out);
    k_reset<<<4, 256>>>();
}

// round 4
// speedup vs baseline: 1.2060x; 1.1199x over previous
#include <cuda_runtime.h>
#include <cstdint>

#define Hc   256
#define Bc   64
#define Tc   256
#define Ec   300
#define NB   128
#define NT   256
typedef unsigned long long ull;

// ---------------- device scratch (no allocations allowed) ----------------
__device__ float g_pre0[(size_t)Tc * 1024 * Bc];   // [t][gatecol 0..1023][b]  (64 MB)
__device__ float g_h0[2][Hc * Bc];                 // layer0 h, double buffered, [unit][b]
__device__ float g_h1[2][Hc * Bc];                 // layer1 h
__device__ unsigned g_flags[NB * 8];               // 32B-padded per-CTA epoch flags
__device__ unsigned g_gen;                         // broadcast generation word
__device__ int g_is64;

// ---------------- helpers ----------------
__device__ __forceinline__ void fma2(ull& d, ull a, ull b) {
    asm("fma.rn.f32x2 %0, %1, %2, %0;" : "+l"(d) : "l"(a), "l"(b));
}
__device__ __forceinline__ ull dup2(float x) {
    ull r;
    asm("mov.b64 %0, {%1, %1};" : "=l"(r) : "f"(x));
    return r;
}
__device__ __forceinline__ float2 unpk(ull v) {
    float2 r;
    asm("mov.b64 {%0, %1}, %2;" : "=f"(r.x), "=f"(r.y) : "l"(v));
    return r;
}
__device__ __forceinline__ float sigf(float x)  { return 1.0f / (1.0f + __expf(-x)); }
__device__ __forceinline__ float tanhf_(float x){ return 2.0f / (1.0f + __expf(-2.0f * x)) - 1.0f; }

__device__ __forceinline__ void st_rel(unsigned* p, unsigned v) {
    asm volatile("st.release.gpu.global.u32 [%0], %1;" :: "l"(p), "r"(v) : "memory");
}
__device__ __forceinline__ unsigned ld_acq(const unsigned* p) {
    unsigned v;
    asm volatile("ld.acquire.gpu.global.u32 %0, [%1];" : "=r"(v) : "l"(p) : "memory");
    return v;
}

// Grid barrier: one release-store per CTA to a padded flag; CTA0/warp0
// aggregates 128 flags and publishes ONE generation word; everyone else spins
// on that single word with one acquire-load per CTA.
__device__ __forceinline__ void gbar(int bid, int tid, unsigned epoch) {
    __syncthreads();                         // CTA-scope cumulativity for h stores
    if (tid == 0) st_rel(&g_flags[bid * 8], epoch);
    if (bid == 0 && tid < 32) {
        bool ok;
        do {
            unsigned v0 = ld_acq(&g_flags[tid * 8]);
            unsigned v1 = ld_acq(&g_flags[(tid + 32) * 8]);
            unsigned v2 = ld_acq(&g_flags[(tid + 64) * 8]);
            unsigned v3 = ld_acq(&g_flags[(tid + 96) * 8]);
            ok = (v0 >= epoch) & (v1 >= epoch) & (v2 >= epoch) & (v3 >= epoch);
        } while (!__all_sync(0xffffffffu, ok));
        if (tid == 0) st_rel(&g_gen, epoch);
    } else if (tid == 0) {
        while (ld_acq(&g_gen) < epoch) {}
    }
    __syncthreads();                         // publish acquire to whole CTA
}

// ---------------- kernel: int32 vs int64 token detector ----------------
__global__ void k_detect(const int* __restrict__ x) {
    int v = 0;
    for (int i = threadIdx.x * 2 + 1; i < Bc * Tc; i += 1024) v |= x[i];
    int any = __syncthreads_or(v);
    if (threadIdx.x == 0) g_is64 = (any == 0) ? 1 : 0;
}

// ---------------- kernel: pre0[t][c][b] = b0[c] + emb[x[b,t]] . W0x[:,c] ----------------
__global__ void __launch_bounds__(256) k_pre(const int* __restrict__ x,
                                             const float* __restrict__ emb,
                                             const float* __restrict__ W0,
                                             const float* __restrict__ b0) {
    extern __shared__ float semb[];  // [Ec][66]
    const int t = blockIdx.y, ct = blockIdx.x;
    const int tid = threadIdx.x, lane = tid & 31, w = tid >> 5;
    const int is64 = g_is64;

    for (int bb = w; bb < Bc; bb += 8) {
        int idx = bb * Tc + t;
        int tok = is64 ? x[2 * idx] : x[idx];
        const float* er = emb + (size_t)tok * Ec;
        for (int e = lane; e < Ec; e += 32) semb[e * 66 + bb] = er[e];
    }
    __syncthreads();

    const int cg = tid & 63, bg = tid >> 6;
    const int c0 = ct * 256 + cg * 4;

    ull a0[8], a1[8], a2[8], a3[8];
#pragma unroll
    for (int j = 0; j < 8; j++) { a0[j] = 0ull; a1[j] = 0ull; a2[j] = 0ull; a3[j] = 0ull; }

#pragma unroll 4
    for (int e = 0; e < Ec; e++) {
        float4 wv = __ldg((const float4*)(W0 + (size_t)e * 1024 + c0));
        ull w0 = dup2(wv.x), w1 = dup2(wv.y), w2 = dup2(wv.z), w3 = dup2(wv.w);
        const ull* sp = (const ull*)(semb + e * 66 + bg * 16);
        ull p0 = sp[0], p1 = sp[1], p2 = sp[2], p3 = sp[3];
        ull p4 = sp[4], p5 = sp[5], p6 = sp[6], p7 = sp[7];
        fma2(a0[0], p0, w0); fma2(a0[1], p1, w0); fma2(a0[2], p2, w0); fma2(a0[3], p3, w0);
        fma2(a0[4], p4, w0); fma2(a0[5], p5, w0); fma2(a0[6], p6, w0); fma2(a0[7], p7, w0);
        fma2(a1[0], p0, w1); fma2(a1[1], p1, w1); fma2(a1[2], p2, w1); fma2(a1[3], p3, w1);
        fma2(a1[4], p4, w1); fma2(a1[5], p5, w1); fma2(a1[6], p6, w1); fma2(a1[7], p7, w1);
        fma2(a2[0], p0, w2); fma2(a2[1], p1, w2); fma2(a2[2], p2, w2); fma2(a2[3], p3, w2);
        fma2(a2[4], p4, w2); fma2(a2[5], p5, w2); fma2(a2[6], p6, w2); fma2(a2[7], p7, w2);
        fma2(a3[0], p0, w3); fma2(a3[1], p1, w3); fma2(a3[2], p2, w3); fma2(a3[3], p3, w3);
        fma2(a3[4], p4, w3); fma2(a3[5], p5, w3); fma2(a3[6], p6, w3); fma2(a3[7], p7, w3);
    }

    float4 bb4 = __ldg((const float4*)(b0 + c0));
    float bs[4] = {bb4.x, bb4.y, bb4.z, bb4.w};
    ull* accs[4] = {a0, a1, a2, a3};
#pragma unroll
    for (int j = 0; j < 4; j++) {
        float* op = g_pre0 + ((size_t)t * 1024 + c0 + j) * Bc + bg * 16;
#pragma unroll
        for (int p = 0; p < 8; p++) {
            float2 v = unpk(accs[j][p]);
            v.x += bs[j]; v.y += bs[j];
            *(float2*)(op + 2 * p) = v;
        }
    }
}

// ---------------- kernel: persistent 2-layer pipelined recurrence ----------------
// 128 CTAs x 256 thr; CTA owns 2 hidden units of BOTH layers for all 64 batches.
// 257 supersteps; layer1 lags layer0 by one step -> one global barrier/superstep.
// h loads are explicitly register-staged in chunks of 16 (MLP=16/warp) so L2
// latency is exposed once per chunk, pipelined against the FMA block.
__global__ void __launch_bounds__(256) k_rnn(const float* __restrict__ W0,
                                             const float* __restrict__ W1,
                                             const float* __restrict__ b1,
                                             float* __restrict__ out) {
    extern __shared__ char sm[];
    ull*   swf  = (ull*)sm;                    // fused weights: [k][16 cols dup'd]  32KB
    ull*   swt  = swf + 256 * 16;              // tail  weights: [k][8 cols dup'd]   16KB
    float* gg   = (float*)(swt + 256 * 8);     // partials [16 cols][8 warps][64 b]  32KB
    float* b1sh = gg + 16 * 8 * 64;

    const int tid = threadIdx.x, lane = tid & 31, w = tid >> 5, bid = blockIdx.x;

    for (int idx = tid; idx < 256 * 8; idx += NT) {
        int k = idx >> 3, c = idx & 7;
        int G = ((c >> 1) << 8) + bid * 2 + (c & 1);
        swf[k * 16 + c]     = dup2(__ldg(W0 + (size_t)(Ec + k) * 1024 + G));  // W0h
        swf[k * 16 + 8 + c] = dup2(__ldg(W1 + (size_t)k * 1024 + G));         // W1x
        swt[k * 8 + c]      = dup2(__ldg(W1 + (size_t)(Hc + k) * 1024 + G));  // W1h
    }
    if (tid < 8) {
        int c = tid;
        int G = ((c >> 1) << 8) + bid * 2 + (c & 1);
        b1sh[c] = __ldg(b1 + G);
    }
    if (tid < 128) {
        int off = bid * 128 + tid;
        g_h0[0][off] = 0.f; g_h0[1][off] = 0.f;
        g_h1[0][off] = 0.f; g_h1[1][off] = 0.f;
    }
    float creg = 0.f;
    gbar(bid, tid, 1u);

    const int l_ = tid >> 7, u_ = (tid >> 6) & 1, b_ = tid & 63;
    const int U_ = bid * 2 + u_;

    for (int s = 0; s <= Tc; s++) {
        const float* rb0 = g_h0[s & 1];
        const float* rb1 = g_h1[s & 1];

        // prefetch this thread's 4 precomputed x-proj gate values
        float pf[4] = {0.f, 0.f, 0.f, 0.f};
        if (l_ == 0 && s < Tc) {
#pragma unroll
            for (int g = 0; g < 4; g++)
                pf[g] = __ldg(g_pre0 + ((size_t)s * 1024 + g * 256 + U_) * Bc + b_);
        }

        ull aA[8], aB[8];
#pragma unroll
        for (int j = 0; j < 8; j++) { aA[j] = 0ull; aB[j] = 0ull; }

        const ull* hp0 = (const ull*)rb0 + w * 32 * 32 + lane;
        const ull* hp1 = (const ull*)rb1 + w * 32 * 32 + lane;
        const ulonglong2* wpf = (const ulonglong2*)(swf + (size_t)w * 32 * 16);
        const ulonglong2* wpt = (const ulonglong2*)(swt + (size_t)w * 32 * 8);

        // fused pass over h0[s-1], two register-staged chunks of 16 k
#pragma unroll
        for (int ch = 0; ch < 2; ch++) {
            ull hv[16];
#pragma unroll
            for (int kk = 0; kk < 16; kk++) hv[kk] = __ldcg(hp0 + (ch * 16 + kk) * 32);
#pragma unroll
            for (int kk = 0; kk < 16; kk++) {
                const ulonglong2* qp = wpf + (ch * 16 + kk) * 8;
                ulonglong2 q0 = qp[0], q1 = qp[1], q2 = qp[2], q3 = qp[3];
                ulonglong2 q4 = qp[4], q5 = qp[5], q6 = qp[6], q7 = qp[7];
                ull hvv = hv[kk];
                fma2(aA[0], hvv, q0.x); fma2(aA[1], hvv, q0.y);
                fma2(aA[2], hvv, q1.x); fma2(aA[3], hvv, q1.y);
                fma2(aA[4], hvv, q2.x); fma2(aA[5], hvv, q2.y);
                fma2(aA[6], hvv, q3.x); fma2(aA[7], hvv, q3.y);
                fma2(aB[0], hvv, q4.x); fma2(aB[1], hvv, q4.y);
                fma2(aB[2], hvv, q5.x); fma2(aB[3], hvv, q5.y);
                fma2(aB[4], hvv, q6.x); fma2(aB[5], hvv, q6.y);
                fma2(aB[6], hvv, q7.x); fma2(aB[7], hvv, q7.y);
            }
        }
        // tail pass over h1[s-2], two register-staged chunks of 16 k
#pragma unroll
        for (int ch = 0; ch < 2; ch++) {
            ull hv[16];
#pragma unroll
            for (int kk = 0; kk < 16; kk++) hv[kk] = __ldcg(hp1 + (ch * 16 + kk) * 32);
#pragma unroll
            for (int kk = 0; kk < 16; kk++) {
                const ulonglong2* qp = wpt + (ch * 16 + kk) * 4;
                ulonglong2 q0 = qp[0], q1 = qp[1], q2 = qp[2], q3 = qp[3];
                ull hvv = hv[kk];
                fma2(aB[0], hvv, q0.x); fma2(aB[1], hvv, q0.y);
                fma2(aB[2], hvv, q1.x); fma2(aB[3], hvv, q1.y);
                fma2(aB[4], hvv, q2.x); fma2(aB[5], hvv, q2.y);
                fma2(aB[6], hvv, q3.x); fma2(aB[7], hvv, q3.y);
            }
        }
#pragma unroll
        for (int c = 0; c < 8; c++) {
            ((ull*)gg)[(c * 8 + w) * 32 + lane]       = aA[c];
            ((ull*)gg)[((8 + c) * 8 + w) * 32 + lane] = aB[c];
        }
        __syncthreads();

        const bool active = (l_ == 0) ? (s < Tc) : (s >= 1);
        if (active) {
            float gate[4];
#pragma unroll
            for (int g = 0; g < 4; g++) {
                int c = l_ * 8 + g * 2 + u_;
                const float* pp = gg + (c * 8) * 64 + b_;
                float sum = pp[0] + pp[64] + pp[128] + pp[192] +
                            pp[256] + pp[320] + pp[384] + pp[448];
                gate[g] = sum + ((l_ == 0) ? pf[g] : b1sh[g * 2 + u_]);
            }
            float ii = sigf(gate[0]);
            float jj = tanhf_(gate[1]);
            float ff = sigf(gate[2] + 1.0f);       // FORGET_BIAS
            float oo = sigf(gate[3]);
            creg = creg * ff + ii * jj;
            float h = tanhf_(creg) * oo;
            if (l_ == 0) {
                g_h0[(s + 1) & 1][U_ * Bc + b_] = h;
            } else if (s < Tc) {
                g_h1[(s + 1) & 1][U_ * Bc + b_] = h;
            } else {
                out[b_ * Hc + U_] = h;             // h1[T-1] -> final output
            }
        }
        if (s < Tc) gbar(bid, tid, (unsigned)(s + 2));
    }
}

// ---------------- kernel: reset barrier state (runs BEFORE k_rnn in-stream) ----------------
__global__ void k_reset() {
    int i = blockIdx.x * blockDim.x + threadIdx.x;
    if (i < NB * 8) g_flags[i] = 0u;
    if (i == 0) g_gen = 0u;
}

// ---------------- host launcher ----------------
extern "C" void kernel_launch(void* const* d_in, const int* in_sizes, int n_in,
                              void* d_out, int out_size) {
    const int*   x   = (const int*)d_in[0];
    const float* emb = (const float*)d_in[1];
    const float* W0  = (const float*)d_in[2];
    const float* b0  = (const float*)d_in[3];
    const float* W1  = (const float*)d_in[4];
    const float* b1  = (const float*)d_in[5];
    float*       out = (float*)d_out;
    (void)in_sizes; (void)n_in; (void)out_size;

    const int smem_pre = Ec * 66 * 4;                              // 79200 B
    const int smem_rnn = 256 * 16 * 8 + 256 * 8 * 8 + 16 * 8 * 64 * 4 + 64;  // ~82 KB

    static bool attr_done = false;
    if (!attr_done) {
        cudaFuncSetAttribute(k_pre, cudaFuncAttributeMaxDynamicSharedMemorySize, smem_pre);
        cudaFuncSetAttribute(k_rnn, cudaFuncAttributeMaxDynamicSharedMemorySize, smem_rnn);
        attr_done = true;
    }

    // order chosen so k_rnn is the 4th launch of the call (profiler lands on it)
    k_detect<<<1, 512>>>(x);
    k_pre<<<dim3(4, 256), 256, smem_pre>>>(x, emb, W0, b0);
    k_reset<<<4, 256>>>();
    k_rnn<<<NB, NT, smem_rnn>>>(W0, W1, b1, out);
}

// round 6
// speedup vs baseline: 1.7673x; 1.4654x over previous
#include <cuda_runtime.h>
#include <cstdint>

#define Hc   256
#define Bc   64
#define Tc   256
#define Ec   300
#define NB   128
#define NT   512          // 16 warps/CTA for latency hiding
#define KPW  16           // k-slice per warp
typedef unsigned long long ull;

// ---------------- device scratch (no allocations allowed) ----------------
__device__ float g_pre0[(size_t)Tc * 1024 * Bc];   // [t][gatecol 0..1023][b]  (64 MB)
__device__ float g_h0[2][Hc * Bc];                 // layer0 h, double buffered, [unit][b]
__device__ float g_h1[2][Hc * Bc];                 // layer1 h
__device__ unsigned g_flags[NB * 8];               // 32B-padded per-CTA epoch flags
__device__ unsigned g_gen;                         // broadcast generation word
__device__ int g_is64;

// ---------------- helpers ----------------
__device__ __forceinline__ void fma2(ull& d, ull a, ull b) {
    asm("fma.rn.f32x2 %0, %1, %2, %0;" : "+l"(d) : "l"(a), "l"(b));
}
__device__ __forceinline__ ull dup2(float x) {
    ull r;
    asm("mov.b64 %0, {%1, %1};" : "=l"(r) : "f"(x));
    return r;
}
__device__ __forceinline__ float2 unpk(ull v) {
    float2 r;
    asm("mov.b64 {%0, %1}, %2;" : "=f"(r.x), "=f"(r.y) : "l"(v));
    return r;
}
__device__ __forceinline__ float sigf(float x)  { return 1.0f / (1.0f + __expf(-x)); }
__device__ __forceinline__ float tanhf_(float x){ return 2.0f / (1.0f + __expf(-2.0f * x)) - 1.0f; }

__device__ __forceinline__ void st_rel(unsigned* p, unsigned v) {
    asm volatile("st.release.gpu.global.u32 [%0], %1;" :: "l"(p), "r"(v) : "memory");
}
__device__ __forceinline__ unsigned ld_acq(const unsigned* p) {
    unsigned v;
    asm volatile("ld.acquire.gpu.global.u32 %0, [%1];" : "=r"(v) : "l"(p) : "memory");
    return v;
}

// Grid barrier: one release-store per CTA; CTA0/warp0 aggregates 128 flags and
// publishes ONE generation word; other CTAs spin on that single word.
__device__ __forceinline__ void gbar(int bid, int tid, unsigned epoch) {
    __syncthreads();
    if (tid == 0) st_rel(&g_flags[bid * 8], epoch);
    if (bid == 0 && tid < 32) {
        bool ok;
        do {
            unsigned v0 = ld_acq(&g_flags[tid * 8]);
            unsigned v1 = ld_acq(&g_flags[(tid + 32) * 8]);
            unsigned v2 = ld_acq(&g_flags[(tid + 64) * 8]);
            unsigned v3 = ld_acq(&g_flags[(tid + 96) * 8]);
            ok = (v0 >= epoch) & (v1 >= epoch) & (v2 >= epoch) & (v3 >= epoch);
        } while (!__all_sync(0xffffffffu, ok));
        if (tid == 0) st_rel(&g_gen, epoch);
    } else if (tid == 0) {
        while (ld_acq(&g_gen) < epoch) {}
    }
    __syncthreads();
}

// ---------------- kernel: int32 vs int64 token detector ----------------
__global__ void k_detect(const int* __restrict__ x) {
    int v = 0;
    for (int i = threadIdx.x * 2 + 1; i < Bc * Tc; i += 1024) v |= x[i];
    int any = __syncthreads_or(v);
    if (threadIdx.x == 0) g_is64 = (any == 0) ? 1 : 0;
}

// ---------------- kernel: pre0[t][c][b] = b0[c] + emb[x[b,t]] . W0x[:,c] ----------------
__global__ void __launch_bounds__(256) k_pre(const int* __restrict__ x,
                                             const float* __restrict__ emb,
                                             const float* __restrict__ W0,
                                             const float* __restrict__ b0) {
    extern __shared__ float semb[];  // [Ec][66]
    const int t = blockIdx.y, ct = blockIdx.x;
    const int tid = threadIdx.x, lane = tid & 31, w = tid >> 5;
    const int is64 = g_is64;

    for (int bb = w; bb < Bc; bb += 8) {
        int idx = bb * Tc + t;
        int tok = is64 ? x[2 * idx] : x[idx];
        const float* er = emb + (size_t)tok * Ec;
        for (int e = lane; e < Ec; e += 32) semb[e * 66 + bb] = er[e];
    }
    __syncthreads();

    const int cg = tid & 63, bg = tid >> 6;
    const int c0 = ct * 256 + cg * 4;

    ull a0[8], a1[8], a2[8], a3[8];
#pragma unroll
    for (int j = 0; j < 8; j++) { a0[j] = 0ull; a1[j] = 0ull; a2[j] = 0ull; a3[j] = 0ull; }

#pragma unroll 4
    for (int e = 0; e < Ec; e++) {
        float4 wv = __ldg((const float4*)(W0 + (size_t)e * 1024 + c0));
        ull w0 = dup2(wv.x), w1 = dup2(wv.y), w2 = dup2(wv.z), w3 = dup2(wv.w);
        const ull* sp = (const ull*)(semb + e * 66 + bg * 16);
        ull p0 = sp[0], p1 = sp[1], p2 = sp[2], p3 = sp[3];
        ull p4 = sp[4], p5 = sp[5], p6 = sp[6], p7 = sp[7];
        fma2(a0[0], p0, w0); fma2(a0[1], p1, w0); fma2(a0[2], p2, w0); fma2(a0[3], p3, w0);
        fma2(a0[4], p4, w0); fma2(a0[5], p5, w0); fma2(a0[6], p6, w0); fma2(a0[7], p7, w0);
        fma2(a1[0], p0, w1); fma2(a1[1], p1, w1); fma2(a1[2], p2, w1); fma2(a1[3], p3, w1);
        fma2(a1[4], p4, w1); fma2(a1[5], p5, w1); fma2(a1[6], p6, w1); fma2(a1[7], p7, w1);
        fma2(a2[0], p0, w2); fma2(a2[1], p1, w2); fma2(a2[2], p2, w2); fma2(a2[3], p3, w2);
        fma2(a2[4], p4, w2); fma2(a2[5], p5, w2); fma2(a2[6], p6, w2); fma2(a2[7], p7, w2);
        fma2(a3[0], p0, w3); fma2(a3[1], p1, w3); fma2(a3[2], p2, w3); fma2(a3[3], p3, w3);
        fma2(a3[4], p4, w3); fma2(a3[5], p5, w3); fma2(a3[6], p6, w3); fma2(a3[7], p7, w3);
    }

    float4 bb4 = __ldg((const float4*)(b0 + c0));
    float bs[4] = {bb4.x, bb4.y, bb4.z, bb4.w};
    ull* accs[4] = {a0, a1, a2, a3};
#pragma unroll
    for (int j = 0; j < 4; j++) {
        float* op = g_pre0 + ((size_t)t * 1024 + c0 + j) * Bc + bg * 16;
#pragma unroll
        for (int p = 0; p < 8; p++) {
            float2 v = unpk(accs[j][p]);
            v.x += bs[j]; v.y += bs[j];
            *(float2*)(op + 2 * p) = v;
        }
    }
}

// ---------------- kernel: persistent 2-layer pipelined recurrence ----------------
// 128 CTAs x 512 thr (16 warps, 4/SMSP for latency hiding). CTA owns 2 hidden
// units of BOTH layers for all 64 batches. 257 supersteps, one grid barrier each.
// Warp w covers k in [16w, 16w+16); lane owns batch pair (2*lane, 2*lane+1).
__global__ void __launch_bounds__(512) k_rnn(const float* __restrict__ W0,
                                             const float* __restrict__ W1,
                                             const float* __restrict__ b1,
                                             float* __restrict__ out) {
    extern __shared__ char sm[];
    ull*   swf  = (ull*)sm;                    // fused weights: [k][16 cols dup'd]  32KB
    ull*   swt  = swf + 256 * 16;              // tail  weights: [k][8 cols dup'd]   16KB
    float* gg   = (float*)(swt + 256 * 8);     // partials [16 cols][16 warps][64 b] 64KB
    float* b1sh = gg + 16 * 16 * 64;

    const int tid = threadIdx.x, lane = tid & 31, w = tid >> 5, bid = blockIdx.x;

    for (int idx = tid; idx < 256 * 8; idx += NT) {
        int k = idx >> 3, c = idx & 7;
        int G = ((c >> 1) << 8) + bid * 2 + (c & 1);
        swf[k * 16 + c]     = dup2(__ldg(W0 + (size_t)(Ec + k) * 1024 + G));  // W0h
        swf[k * 16 + 8 + c] = dup2(__ldg(W1 + (size_t)k * 1024 + G));         // W1x
        swt[k * 8 + c]      = dup2(__ldg(W1 + (size_t)(Hc + k) * 1024 + G));  // W1h
    }
    if (tid < 8) {
        int c = tid;
        int G = ((c >> 1) << 8) + bid * 2 + (c & 1);
        b1sh[c] = __ldg(b1 + G);
    }
    if (tid < 128) {
        int off = bid * 128 + tid;
        g_h0[0][off] = 0.f; g_h0[1][off] = 0.f;
        g_h1[0][off] = 0.f; g_h1[1][off] = 0.f;
    }
    float creg = 0.f;
    gbar(bid, tid, 1u);

    const int l_ = tid >> 7, u_ = (tid >> 6) & 1, b_ = tid & 63;   // tid<256 only
    const int U_ = bid * 2 + u_;

    for (int s = 0; s <= Tc; s++) {
        const float* rb0 = g_h0[s & 1];
        const float* rb1 = g_h1[s & 1];

        // prefetch this thread's 4 precomputed x-proj gate values
        float pf[4] = {0.f, 0.f, 0.f, 0.f};
        if (tid < 256 && l_ == 0 && s < Tc) {
#pragma unroll
            for (int g = 0; g < 4; g++)
                pf[g] = __ldg(g_pre0 + ((size_t)s * 1024 + g * 256 + U_) * Bc + b_);
        }

        ull aA[8], aB[8];
#pragma unroll
        for (int j = 0; j < 8; j++) { aA[j] = 0ull; aB[j] = 0ull; }

        const ull* hp0 = (const ull*)rb0 + (w * KPW) * 32 + lane;
        const ull* hp1 = (const ull*)rb1 + (w * KPW) * 32 + lane;
        const ulonglong2* wpf = (const ulonglong2*)(swf + (size_t)w * KPW * 16);
        const ulonglong2* wpt = (const ulonglong2*)(swt + (size_t)w * KPW * 8);

        {   // fused pass over h0[s-1]: 16 k, register-staged (MLP=16)
            ull hv[KPW];
#pragma unroll
            for (int kk = 0; kk < KPW; kk++) hv[kk] = __ldcg(hp0 + kk * 32);
#pragma unroll
            for (int kk = 0; kk < KPW; kk++) {
                const ulonglong2* qp = wpf + kk * 8;
                ulonglong2 q0 = qp[0], q1 = qp[1], q2 = qp[2], q3 = qp[3];
                ulonglong2 q4 = qp[4], q5 = qp[5], q6 = qp[6], q7 = qp[7];
                ull hvv = hv[kk];
                fma2(aA[0], hvv, q0.x); fma2(aA[1], hvv, q0.y);
                fma2(aA[2], hvv, q1.x); fma2(aA[3], hvv, q1.y);
                fma2(aA[4], hvv, q2.x); fma2(aA[5], hvv, q2.y);
                fma2(aA[6], hvv, q3.x); fma2(aA[7], hvv, q3.y);
                fma2(aB[0], hvv, q4.x); fma2(aB[1], hvv, q4.y);
                fma2(aB[2], hvv, q5.x); fma2(aB[3], hvv, q5.y);
                fma2(aB[4], hvv, q6.x); fma2(aB[5], hvv, q6.y);
                fma2(aB[6], hvv, q7.x); fma2(aB[7], hvv, q7.y);
            }
        }
        {   // tail pass over h1[s-2]: 16 k, register-staged
            ull hv[KPW];
#pragma unroll
            for (int kk = 0; kk < KPW; kk++) hv[kk] = __ldcg(hp1 + kk * 32);
#pragma unroll
            for (int kk = 0; kk < KPW; kk++) {
                const ulonglong2* qp = wpt + kk * 4;
                ulonglong2 q0 = qp[0], q1 = qp[1], q2 = qp[2], q3 = qp[3];
                ull hvv = hv[kk];
                fma2(aB[0], hvv, q0.x); fma2(aB[1], hvv, q0.y);
                fma2(aB[2], hvv, q1.x); fma2(aB[3], hvv, q1.y);
                fma2(aB[4], hvv, q2.x); fma2(aB[5], hvv, q2.y);
                fma2(aB[6], hvv, q3.x); fma2(aB[7], hvv, q3.y);
            }
        }
        // publish split-K partials: gg[col][warp][batch]
#pragma unroll
        for (int c = 0; c < 8; c++) {
            ((ull*)gg)[(c * 16 + w) * 32 + lane]       = aA[c];
            ((ull*)gg)[((8 + c) * 16 + w) * 32 + lane] = aB[c];
        }
        __syncthreads();

        const bool active = (tid < 256) && ((l_ == 0) ? (s < Tc) : (s >= 1));
        if (active) {
            float gate[4];
#pragma unroll
            for (int g = 0; g < 4; g++) {
                int c = l_ * 8 + g * 2 + u_;
                const float* pp = gg + (c * 16) * 64 + b_;
                float sum = 0.f;
#pragma unroll
                for (int ww = 0; ww < 16; ww++) sum += pp[ww * 64];
                gate[g] = sum + ((l_ == 0) ? pf[g] : b1sh[g * 2 + u_]);
            }
            float ii = sigf(gate[0]);
            float jj = tanhf_(gate[1]);
            float ff = sigf(gate[2] + 1.0f);       // FORGET_BIAS
            float oo = sigf(gate[3]);
            creg = creg * ff + ii * jj;
            float h = tanhf_(creg) * oo;
            if (l_ == 0) {
                g_h0[(s + 1) & 1][U_ * Bc + b_] = h;
            } else if (s < Tc) {
                g_h1[(s + 1) & 1][U_ * Bc + b_] = h;
            } else {
                out[b_ * Hc + U_] = h;             // h1[T-1] -> final output
            }
        }
        if (s < Tc) gbar(bid, tid, (unsigned)(s + 2));
    }
}

// ---------------- kernel: reset barrier state (runs BEFORE k_rnn in-stream) ----------------
__global__ void k_reset() {
    int i = blockIdx.x * blockDim.x + threadIdx.x;
    if (i < NB * 8) g_flags[i] = 0u;
    if (i == 0) g_gen = 0u;
}

// ---------------- host launcher ----------------
extern "C" void kernel_launch(void* const* d_in, const int* in_sizes, int n_in,
                              void* d_out, int out_size) {
    const int*   x   = (const int*)d_in[0];
    const float* emb = (const float*)d_in[1];
    const float* W0  = (const float*)d_in[2];
    const float* b0  = (const float*)d_in[3];
    const float* W1  = (const float*)d_in[4];
    const float* b1  = (const float*)d_in[5];
    float*       out = (float*)d_out;
    (void)in_sizes; (void)n_in; (void)out_size;

    const int smem_pre = Ec * 66 * 4;                                   // 79200 B
    const int smem_rnn = 256 * 16 * 8 + 256 * 8 * 8 + 16 * 16 * 64 * 4 + 64;  // ~114.8 KB

    static bool attr_done = false;
    if (!attr_done) {
        cudaFuncSetAttribute(k_pre, cudaFuncAttributeMaxDynamicSharedMemorySize, smem_pre);
        cudaFuncSetAttribute(k_rnn, cudaFuncAttributeMaxDynamicSharedMemorySize, smem_rnn);
        attr_done = true;
    }

    // order kept so the profiler lands on k_rnn
    k_detect<<<1, 512>>>(x);
    k_pre<<<dim3(4, 256), 256, smem_pre>>>(x, emb, W0, b0);
    k_reset<<<4, 256>>>();
    k_rnn<<<NB, NT, smem_rnn>>>(W0, W1, b1, out);
}